// round 10
// baseline (speedup 1.0000x reference)
#include <cuda_runtime.h>
#include <math.h>

// Problem constants
//   outputs/targets:           [4, 3, 256, 256]  -> 786432 floats
//   output/target features:    [4, 256, 64, 64]  -> B=4, C=256, N=4096
#define Bn   4
#define Cn   256
#define Nn   4096
#define IMG_ELEMS  786432
#define FEAT_ELEMS 4194304
#define EPS1 1e-8f
#define EPS2 1e-5f

// ---------------- device scratch (allocation-free: static globals) ----------
static __device__ float  g_X[Bn * Nn * Cn];          // centered out-features [b][n][c]
static __device__ float  g_Y[Bn * Nn * Cn];          // centered tgt-features [b][n][c]
static __device__ float  g_mean[2][Bn * Cn];         // per-(b,c) means, [0]=out [1]=tgt
static __device__ float  g_xn[Bn * Nn];              // row norms of X
static __device__ float  g_yn[Bn * Nn];              // row norms of Y
static __device__ float  g_cos[(size_t)Bn * Nn * Nn];// 256 MB cosine matrix [b][x][y]
static __device__ float  g_pS[Bn * Nn];              // per-row scale s = 1/(dmin+eps2)
static __device__ float  g_pA[Bn * Nn];              // per-row affine (1-s) - log(rowsum)
static __device__ float  g_cmax[8 * Bn * Nn];        // partial col maxima (8 x-chunks)
static __device__ double g_msep[2][512];             // MSE block partials

// ---------------- f32x2 packed-FMA helpers ----------------------------------
__device__ __forceinline__ unsigned long long pk2(float lo, float hi) {
    unsigned long long r;
    asm("mov.b64 %0, {%1,%2};" : "=l"(r)
        : "r"(__float_as_uint(lo)), "r"(__float_as_uint(hi)));
    return r;
}
__device__ __forceinline__ unsigned long long bc2(float v) { return pk2(v, v); }
__device__ __forceinline__ void fma2(unsigned long long& d, unsigned long long a,
                                     unsigned long long b) {
    asm("fma.rn.f32x2 %0, %1, %2, %3;" : "=l"(d) : "l"(a), "l"(b), "l"(d));
}
__device__ __forceinline__ void unpk2(unsigned long long p, float& lo, float& hi) {
    unsigned int l, h;
    asm("mov.b64 {%0,%1}, %2;" : "=r"(l), "=r"(h) : "l"(p));
    lo = __uint_as_float(l);
    hi = __uint_as_float(h);
}

// ---------------- 1. MSE partials (deterministic two-stage) ------------------
__global__ void __launch_bounds__(256) mse_kernel(const float* __restrict__ o,
                                                  const float* __restrict__ t,
                                                  const float* __restrict__ of,
                                                  const float* __restrict__ tf) {
    const int which = blockIdx.y;
    const float* a = which ? of : o;
    const float* c = which ? tf : t;
    const int n = which ? FEAT_ELEMS : IMG_ELEMS;
    double s = 0.0;
    for (int i = blockIdx.x * 256 + threadIdx.x; i < n; i += 512 * 256) {
        float d = a[i] - c[i];
        s += (double)d * (double)d;
    }
    __shared__ double sh[256];
    sh[threadIdx.x] = s;
    __syncthreads();
    for (int st = 128; st > 0; st >>= 1) {
        if (threadIdx.x < st) sh[threadIdx.x] += sh[threadIdx.x + st];
        __syncthreads();
    }
    if (threadIdx.x == 0) g_msep[which][blockIdx.x] = sh[0];
}

// ---------------- 2. per-(b,c) means over N positions ------------------------
__global__ void __launch_bounds__(256) mean_kernel(const float* __restrict__ of,
                                                   const float* __restrict__ tf) {
    const float* src = blockIdx.y ? tf : of;
    const int bc = blockIdx.x;  // b*Cn + c
    const float* p = src + (size_t)bc * Nn;
    float s = 0.f;
    for (int i = threadIdx.x; i < Nn; i += 256) s += p[i];
    __shared__ float sh[256];
    sh[threadIdx.x] = s;
    __syncthreads();
    for (int st = 128; st > 0; st >>= 1) {
        if (threadIdx.x < st) sh[threadIdx.x] += sh[threadIdx.x + st];
        __syncthreads();
    }
    if (threadIdx.x == 0) g_mean[blockIdx.y][bc] = sh[0] * (1.f / Nn);
}

// ---------------- 3. transpose [C][N] -> [N][C] with centering ---------------
__global__ void __launch_bounds__(256) transpose_kernel(const float* __restrict__ of,
                                                        const float* __restrict__ tf) {
    const int tz = blockIdx.z;
    const int tensor = tz >> 2;
    const int b = tz & 3;
    const float* src = (tensor ? tf : of) + (size_t)b * Cn * Nn;
    float* dst = (tensor ? g_Y : g_X) + (size_t)b * Nn * Cn;
    const float* mean = g_mean[tensor] + b * Cn;
    __shared__ float tile[32][33];
    const int tx = threadIdx.x, ty = threadIdx.y;  // 32 x 8
    const int n0 = blockIdx.x * 32, c0 = blockIdx.y * 32;
#pragma unroll
    for (int j = 0; j < 4; j++) {
        int c = c0 + ty + j * 8;
        tile[ty + j * 8][tx] = src[(size_t)c * Nn + n0 + tx] - mean[c];
    }
    __syncthreads();
#pragma unroll
    for (int j = 0; j < 4; j++) {
        int n = n0 + ty + j * 8;
        dst[(size_t)n * Cn + c0 + tx] = tile[tx][ty + j * 8];
    }
}

// ---------------- 4. per-row L2 norms ---------------------------------------
__global__ void __launch_bounds__(256) norm_kernel() {
    const int tensor = blockIdx.y;
    const float* X = tensor ? g_Y : g_X;
    float* out = tensor ? g_yn : g_xn;
    const int warp = threadIdx.x >> 5, lane = threadIdx.x & 31;
    const int r = blockIdx.x * 8 + warp;  // 0..16383
    const float4* p = (const float4*)(X + (size_t)r * Cn);
    float s = 0.f;
    float4 v = p[lane];
    s += v.x * v.x + v.y * v.y + v.z * v.z + v.w * v.w;
    v = p[lane + 32];
    s += v.x * v.x + v.y * v.y + v.z * v.z + v.w * v.w;
    for (int o = 16; o; o >>= 1) s += __shfl_xor_sync(0xffffffffu, s, o);
    if (lane == 0) out[r] = sqrtf(s);
}

// ---------------- 5. GEMM: cos[b][x][y] = <X_x,Y_y>/(xn*yn+eps1) -------------
// 128x128 tile, BK=8, 256 threads, 8x8 per thread, f32x2 packed FMAs,
// double-buffered smem.
__global__ void __launch_bounds__(256, 1) gemm_kernel() {
    const int b = blockIdx.z;
    const float* __restrict__ A = g_X + (size_t)b * (Nn * Cn);
    const float* __restrict__ Bm = g_Y + (size_t)b * (Nn * Cn);
    float* __restrict__ C = g_cos + (size_t)b * ((size_t)Nn * Nn);
    const int tid = threadIdx.x;
    const int rowBase = blockIdx.y * 128, colBase = blockIdx.x * 128;
    __shared__ float As[2][8][128];
    __shared__ float Bs[2][8][128];
    const int lr = tid >> 1;
    const int lc = (tid & 1) << 2;
    const float* Ap = A + (size_t)(rowBase + lr) * Cn + lc;
    const float* Bp = Bm + (size_t)(colBase + lr) * Cn + lc;

    float4 ra = *(const float4*)Ap;
    float4 rb = *(const float4*)Bp;
    As[0][lc + 0][lr] = ra.x; As[0][lc + 1][lr] = ra.y;
    As[0][lc + 2][lr] = ra.z; As[0][lc + 3][lr] = ra.w;
    Bs[0][lc + 0][lr] = rb.x; Bs[0][lc + 1][lr] = rb.y;
    Bs[0][lc + 2][lr] = rb.z; Bs[0][lc + 3][lr] = rb.w;
    __syncthreads();

    unsigned long long acc[8][4];
#pragma unroll
    for (int i = 0; i < 8; i++)
#pragma unroll
        for (int j = 0; j < 4; j++) acc[i][j] = 0ull;

    const int trow = tid >> 4, tcol = tid & 15;
    const int ar = trow << 3, bcc = tcol << 3;

    for (int kt = 0; kt < 32; kt++) {
        const int cur = kt & 1;
        float4 na, nb;
        if (kt < 31) {
            na = *(const float4*)(Ap + (kt + 1) * 8);
            nb = *(const float4*)(Bp + (kt + 1) * 8);
        }
#pragma unroll
        for (int k = 0; k < 8; k++) {
            const float4 a0 = *(const float4*)&As[cur][k][ar];
            const float4 a1 = *(const float4*)&As[cur][k][ar + 4];
            const ulonglong2 b0 = *(const ulonglong2*)&Bs[cur][k][bcc];
            const ulonglong2 b1 = *(const ulonglong2*)&Bs[cur][k][bcc + 4];
            unsigned long long av;
            av = bc2(a0.x);
            fma2(acc[0][0], av, b0.x); fma2(acc[0][1], av, b0.y);
            fma2(acc[0][2], av, b1.x); fma2(acc[0][3], av, b1.y);
            av = bc2(a0.y);
            fma2(acc[1][0], av, b0.x); fma2(acc[1][1], av, b0.y);
            fma2(acc[1][2], av, b1.x); fma2(acc[1][3], av, b1.y);
            av = bc2(a0.z);
            fma2(acc[2][0], av, b0.x); fma2(acc[2][1], av, b0.y);
            fma2(acc[2][2], av, b1.x); fma2(acc[2][3], av, b1.y);
            av = bc2(a0.w);
            fma2(acc[3][0], av, b0.x); fma2(acc[3][1], av, b0.y);
            fma2(acc[3][2], av, b1.x); fma2(acc[3][3], av, b1.y);
            av = bc2(a1.x);
            fma2(acc[4][0], av, b0.x); fma2(acc[4][1], av, b0.y);
            fma2(acc[4][2], av, b1.x); fma2(acc[4][3], av, b1.y);
            av = bc2(a1.y);
            fma2(acc[5][0], av, b0.x); fma2(acc[5][1], av, b0.y);
            fma2(acc[5][2], av, b1.x); fma2(acc[5][3], av, b1.y);
            av = bc2(a1.z);
            fma2(acc[6][0], av, b0.x); fma2(acc[6][1], av, b0.y);
            fma2(acc[6][2], av, b1.x); fma2(acc[6][3], av, b1.y);
            av = bc2(a1.w);
            fma2(acc[7][0], av, b0.x); fma2(acc[7][1], av, b0.y);
            fma2(acc[7][2], av, b1.x); fma2(acc[7][3], av, b1.y);
        }
        if (kt < 31) {
            const int nxt = cur ^ 1;
            As[nxt][lc + 0][lr] = na.x; As[nxt][lc + 1][lr] = na.y;
            As[nxt][lc + 2][lr] = na.z; As[nxt][lc + 3][lr] = na.w;
            Bs[nxt][lc + 0][lr] = nb.x; Bs[nxt][lc + 1][lr] = nb.y;
            Bs[nxt][lc + 2][lr] = nb.z; Bs[nxt][lc + 3][lr] = nb.w;
            __syncthreads();
        }
    }

    // epilogue: normalize to cosine, vectorized stores
    const float* xn = g_xn + (b << 12);
    const float* yn = g_yn + (b << 12);
    float ynv[8];
#pragma unroll
    for (int j = 0; j < 8; j++) ynv[j] = yn[colBase + bcc + j];
#pragma unroll
    for (int i = 0; i < 8; i++) {
        const int x = rowBase + ar + i;
        const float xv = xn[x];
        float out[8];
#pragma unroll
        for (int j = 0; j < 4; j++) {
            float lo, hi;
            unpk2(acc[i][j], lo, hi);
            out[2 * j]     = lo / (xv * ynv[2 * j] + EPS1);
            out[2 * j + 1] = hi / (xv * ynv[2 * j + 1] + EPS1);
        }
        float* cp = C + (size_t)x * Nn + colBase + bcc;
        *(float4*)cp       = make_float4(out[0], out[1], out[2], out[3]);
        *(float4*)(cp + 4) = make_float4(out[4], out[5], out[6], out[7]);
    }
}

// ---------------- 6. row pass: rowmax(cos), softmax denom --------------------
// d = 1-cos; dmin = 1-cosmax; s = 1/(dmin+eps2)
// w_y = exp(1 - d_y*s) = exp((1-s) + cos_y*s); store s and (1-s)-log(sum w)
__global__ void __launch_bounds__(256) rowpass_kernel() {
    const int r = blockIdx.x;  // b*Nn + x
    const float* row = g_cos + (size_t)r * Nn;
    __shared__ float sh[Nn];
    __shared__ float red[256];
    const int tid = threadIdx.x;
    float m = -1e30f;
#pragma unroll
    for (int j = 0; j < 16; j++) {
        float v = row[tid + (j << 8)];
        sh[tid + (j << 8)] = v;
        m = fmaxf(m, v);
    }
    red[tid] = m;
    __syncthreads();
    for (int st = 128; st > 0; st >>= 1) {
        if (tid < st) red[tid] = fmaxf(red[tid], red[tid + st]);
        __syncthreads();
    }
    const float cmax = red[0];
    __syncthreads();
    const float s = 1.f / (1.f - cmax + EPS2);
    const float a = 1.f - s;
    float sum = 0.f;
#pragma unroll
    for (int j = 0; j < 16; j++) sum += __expf(fmaf(sh[tid + (j << 8)], s, a));
    red[tid] = sum;
    __syncthreads();
    for (int st = 128; st > 0; st >>= 1) {
        if (tid < st) red[tid] += red[tid + st];
        __syncthreads();
    }
    if (tid == 0) {
        g_pS[r] = s;
        g_pA[r] = a - logf(red[0]);
    }
}

// ---------------- 7. column pass: partial max over x (log-domain) ------------
// log c[x][y] = cos*s_x + A_x  -> max over x chunk of 512, no exp per element
__global__ void __launch_bounds__(256) colpass_kernel() {
    const int y = (blockIdx.x << 8) + threadIdx.x;  // 0..4095
    const int chunk = blockIdx.y;                   // 0..7
    const int b = blockIdx.z;                       // 0..3
    __shared__ float ss[512], sa[512];
    const int r0 = (b << 12) + (chunk << 9);
    for (int i = threadIdx.x; i < 512; i += 256) {
        ss[i] = g_pS[r0 + i];
        sa[i] = g_pA[r0 + i];
    }
    __syncthreads();
    const float* base = g_cos + ((size_t)b << 24) + ((size_t)chunk << 21) + y;
    float m = -1e30f;
#pragma unroll 8
    for (int x = 0; x < 512; x++) {
        m = fmaxf(m, fmaf(base[(size_t)x << 12], ss[x], sa[x]));
    }
    g_cmax[(chunk << 14) + (b << 12) + y] = m;
}

// ---------------- 8. final: CS, MSEs, loss -----------------------------------
__global__ void __launch_bounds__(256) final_kernel(float* __restrict__ out) {
    const int tid = threadIdx.x;
    double cs = 0.0;
    for (int i = tid; i < Bn * Nn; i += 256) {
        float m = -1e30f;
#pragma unroll
        for (int ch = 0; ch < 8; ch++) m = fmaxf(m, g_cmax[(ch << 14) + i]);
        cs += exp((double)m);
    }
    double m1 = 0.0, m2 = 0.0;
    for (int i = tid; i < 512; i += 256) {
        m1 += g_msep[0][i];
        m2 += g_msep[1][i];
    }
    __shared__ double sh[3][256];
    sh[0][tid] = cs; sh[1][tid] = m1; sh[2][tid] = m2;
    __syncthreads();
    for (int st = 128; st > 0; st >>= 1) {
        if (tid < st) {
            sh[0][tid] += sh[0][tid + st];
            sh[1][tid] += sh[1][tid + st];
            sh[2][tid] += sh[2][tid + st];
        }
        __syncthreads();
    }
    if (tid == 0) {
        double CS = sh[0][0] / (double)(Bn * Nn);
        double mse1 = sh[1][0] / (double)IMG_ELEMS;
        double perc = sh[2][0] / (double)FEAT_ELEMS;
        out[0] = (float)(mse1 - log(CS) + 0.02 * perc);
    }
}

// ---------------- launch ------------------------------------------------------
extern "C" void kernel_launch(void* const* d_in, const int* in_sizes, int n_in,
                              void* d_out, int out_size) {
    const float* outputs = (const float*)d_in[0];
    const float* targets = (const float*)d_in[1];
    const float* of = (const float*)d_in[2];
    const float* tf = (const float*)d_in[3];
    float* out = (float*)d_out;

    mse_kernel<<<dim3(512, 2), 256>>>(outputs, targets, of, tf);
    mean_kernel<<<dim3(Bn * Cn, 2), 256>>>(of, tf);
    transpose_kernel<<<dim3(Nn / 32, Cn / 32, 2 * Bn), dim3(32, 8)>>>(of, tf);
    norm_kernel<<<dim3(Bn * Nn / 8, 2), 256>>>();
    gemm_kernel<<<dim3(Nn / 128, Nn / 128, Bn), 256>>>();
    rowpass_kernel<<<Bn * Nn, 256>>>();
    colpass_kernel<<<dim3(Nn / 256, 8, Bn), 256>>>();
    final_kernel<<<1, 256>>>(out);
}

// round 12
// speedup vs baseline: 2.0498x; 2.0498x over previous
#include <cuda_runtime.h>
#include <math.h>
#include <cstdint>

// Problem constants
//   outputs/targets:           [4, 3, 256, 256]  -> 786432 floats
//   output/target features:    [4, 256, 64, 64]  -> B=4, C=256, N=4096
#define Bn   4
#define Cn   256
#define Nn   4096
#define IMG_ELEMS  786432
#define FEAT_ELEMS 4194304
#define EPS1 1e-8f
#define EPS2 1e-5f

// ---------------- device scratch (allocation-free: static globals) ----------
static __device__ float  g_X[Bn * Nn * Cn];          // centered out-features [b][n][c]
static __device__ float  g_Y[Bn * Nn * Cn];          // centered tgt-features [b][n][c]
static __device__ float  g_mean[2][Bn * Cn];         // per-(b,c) means
static __device__ float  g_xn[Bn * Nn];              // row norms of X
static __device__ float  g_yn[Bn * Nn];              // row norms of Y
static __device__ float  g_cos[(size_t)Bn * Nn * Nn];// 256 MB cosine matrix [b][x][y]
static __device__ float  g_pS[Bn * Nn];              // per-row scale s = 1/(dmin+eps2)
static __device__ float  g_pA[Bn * Nn];              // per-row affine (1-s)-log(rowsum)
static __device__ float  g_cmax[8 * Bn * Nn];        // partial col maxima (8 x-chunks)
static __device__ double g_msep[2][512];             // MSE block partials

// ---------------- cp.async helpers (sm_80 baseline — legal on compute_103) --
__device__ __forceinline__ uint32_t smem_u32(const void* p) {
    uint32_t a;
    asm("{ .reg .u64 t; cvta.to.shared.u64 t, %1; cvt.u32.u64 %0, t; }"
        : "=r"(a) : "l"(p));
    return a;
}
#define CP_ASYNC16(dst, src) \
    asm volatile("cp.async.cg.shared.global [%0], [%1], 16;" \
                 :: "r"(dst), "l"(src) : "memory")
#define CP_COMMIT() asm volatile("cp.async.commit_group;" ::: "memory")
#define CP_WAIT(n)  asm volatile("cp.async.wait_group %0;" :: "n"(n) : "memory")

// warp-level tf32 MMA: D(16x8) += A(16x8) * B(8x8), A row-major, B col-major
__device__ __forceinline__ void mma_tf32(float* d, const uint32_t* a,
                                         const uint32_t* b) {
    asm volatile(
        "mma.sync.aligned.m16n8k8.row.col.f32.tf32.tf32.f32 "
        "{%0,%1,%2,%3}, {%4,%5,%6,%7}, {%8,%9}, {%0,%1,%2,%3};"
        : "+f"(d[0]), "+f"(d[1]), "+f"(d[2]), "+f"(d[3])
        : "r"(a[0]), "r"(a[1]), "r"(a[2]), "r"(a[3]), "r"(b[0]), "r"(b[1]));
}

// ---------------- 1. MSE partials (deterministic two-stage) ------------------
__global__ void __launch_bounds__(256) mse_kernel(const float* __restrict__ o,
                                                  const float* __restrict__ t,
                                                  const float* __restrict__ of,
                                                  const float* __restrict__ tf) {
    const int which = blockIdx.y;
    const float* a = which ? of : o;
    const float* c = which ? tf : t;
    const int n = which ? FEAT_ELEMS : IMG_ELEMS;
    double s = 0.0;
    for (int i = blockIdx.x * 256 + threadIdx.x; i < n; i += 512 * 256) {
        float d = a[i] - c[i];
        s += (double)d * (double)d;
    }
    __shared__ double sh[256];
    sh[threadIdx.x] = s;
    __syncthreads();
    for (int st = 128; st > 0; st >>= 1) {
        if (threadIdx.x < st) sh[threadIdx.x] += sh[threadIdx.x + st];
        __syncthreads();
    }
    if (threadIdx.x == 0) g_msep[which][blockIdx.x] = sh[0];
}

// ---------------- 2. per-(b,c) means over N positions ------------------------
__global__ void __launch_bounds__(256) mean_kernel(const float* __restrict__ of,
                                                   const float* __restrict__ tf) {
    const float* src = blockIdx.y ? tf : of;
    const int bc = blockIdx.x;
    const float* p = src + (size_t)bc * Nn;
    float s = 0.f;
    for (int i = threadIdx.x; i < Nn; i += 256) s += p[i];
    __shared__ float sh[256];
    sh[threadIdx.x] = s;
    __syncthreads();
    for (int st = 128; st > 0; st >>= 1) {
        if (threadIdx.x < st) sh[threadIdx.x] += sh[threadIdx.x + st];
        __syncthreads();
    }
    if (threadIdx.x == 0) g_mean[blockIdx.y][bc] = sh[0] * (1.f / Nn);
}

// ---------------- 3. transpose [C][N] -> [N][C] with centering ---------------
__global__ void __launch_bounds__(256) transpose_kernel(const float* __restrict__ of,
                                                        const float* __restrict__ tf) {
    const int tz = blockIdx.z;
    const int tensor = tz >> 2;
    const int b = tz & 3;
    const float* src = (tensor ? tf : of) + (size_t)b * Cn * Nn;
    float* dst = (tensor ? g_Y : g_X) + (size_t)b * Nn * Cn;
    const float* mean = g_mean[tensor] + b * Cn;
    __shared__ float tile[32][33];
    const int tx = threadIdx.x, ty = threadIdx.y;  // 32 x 8
    const int n0 = blockIdx.x * 32, c0 = blockIdx.y * 32;
#pragma unroll
    for (int j = 0; j < 4; j++) {
        int c = c0 + ty + j * 8;
        tile[ty + j * 8][tx] = src[(size_t)c * Nn + n0 + tx] - mean[c];
    }
    __syncthreads();
#pragma unroll
    for (int j = 0; j < 4; j++) {
        int n = n0 + ty + j * 8;
        dst[(size_t)n * Cn + c0 + tx] = tile[tx][ty + j * 8];
    }
}

// ---------------- 4. per-row L2 norms ---------------------------------------
__global__ void __launch_bounds__(256) norm_kernel() {
    const int tensor = blockIdx.y;
    const float* X = tensor ? g_Y : g_X;
    float* out = tensor ? g_yn : g_xn;
    const int warp = threadIdx.x >> 5, lane = threadIdx.x & 31;
    const int r = blockIdx.x * 8 + warp;
    const float4* p = (const float4*)(X + (size_t)r * Cn);
    float s = 0.f;
    float4 v = p[lane];
    s += v.x * v.x + v.y * v.y + v.z * v.z + v.w * v.w;
    v = p[lane + 32];
    s += v.x * v.x + v.y * v.y + v.z * v.z + v.w * v.w;
    for (int o = 16; o; o >>= 1) s += __shfl_xor_sync(0xffffffffu, s, o);
    if (lane == 0) out[r] = sqrtf(s);
}

// ---------------- 5. tf32 mma.sync GEMM -> cosine matrix ---------------------
// BM=128, BN=128, BK=32, 256 threads (8 warps, 2x4 warp grid, warp tile 64x32).
// Per warp: 4 m-tiles x 4 n-tiles of m16n8k8. cp.async double-buffered smem.
// Smem pitch 36 floats -> fragment LDS bank = (4g + c) % 32, conflict-free.
#define SPITCH 36
#define ABUF   4608   // 128 * 36 floats per buffer
__global__ void __launch_bounds__(256) gemm_mma_kernel() {
    extern __shared__ float smem[];  // [A0 | A1 | B0 | B1], 4*4608 floats

    const int b = blockIdx.z;
    const int rowBase = blockIdx.y * 128, colBase = blockIdx.x * 128;
    const float* __restrict__ A  = g_X + (size_t)b * (Nn * Cn);
    const float* __restrict__ Bm = g_Y + (size_t)b * (Nn * Cn);
    const int tid = threadIdx.x;
    const int wid = tid >> 5, lane = tid & 31;
    const int wm = wid & 1, wn = wid >> 1;   // 2 along M, 4 along N
    const int g = lane >> 2, c = lane & 3;

    // ---- cp.async staging geometry (chunk = 128 rows x 32 cols) ----
    const int cg = (tid & 7) * 4;            // col group 0,4,..,28
    const int row0 = tid >> 3;               // rows row0 + 32*t, t=0..3
    const uint32_t sbase = smem_u32(smem);
    const float* Agp = A + (size_t)(rowBase + row0) * Cn + cg;
    const float* Bgp = Bm + (size_t)(colBase + row0) * Cn + cg;
    const uint32_t sAoff = (uint32_t)(row0 * SPITCH + cg) * 4;

    // issue chunk ch into buffer buf
#define ISSUE(ch, buf) do {                                                   \
        const uint32_t dA = sbase + (buf) * (ABUF * 4) + sAoff;               \
        const uint32_t dB = sbase + (2 * ABUF + (buf) * ABUF) * 4 + sAoff;    \
        _Pragma("unroll")                                                     \
        for (int t = 0; t < 4; t++) {                                         \
            CP_ASYNC16(dA + t * (32 * SPITCH * 4), Agp + t * 32 * Cn + (ch) * 32); \
            CP_ASYNC16(dB + t * (32 * SPITCH * 4), Bgp + t * 32 * Cn + (ch) * 32); \
        }                                                                     \
        CP_COMMIT();                                                          \
    } while (0)

    float d[4][4][4];
#pragma unroll
    for (int mt = 0; mt < 4; mt++)
#pragma unroll
        for (int nt = 0; nt < 4; nt++)
#pragma unroll
            for (int k = 0; k < 4; k++) d[mt][nt][k] = 0.f;

    const int aBase = (wm * 64 + g) * SPITCH + c;
    const int bBase = (wn * 32 + g) * SPITCH + c;

    ISSUE(0, 0);
    for (int ch = 0; ch < 8; ch++) {
        if (ch < 7) {
            ISSUE(ch + 1, (ch + 1) & 1);
            CP_WAIT(1);
        } else {
            CP_WAIT(0);
        }
        __syncthreads();

        const int cur = ch & 1;
        const float* Asb = smem + cur * ABUF;
        const float* Bsb = smem + 2 * ABUF + cur * ABUF;
#pragma unroll
        for (int kk = 0; kk < 4; kk++) {
            const int kb = kk * 8;
            uint32_t af[4][4], bf[4][2];
#pragma unroll
            for (int mt = 0; mt < 4; mt++) {
                const float* p = Asb + aBase + mt * (16 * SPITCH) + kb;
                af[mt][0] = __float_as_uint(p[0]);
                af[mt][1] = __float_as_uint(p[8 * SPITCH]);
                af[mt][2] = __float_as_uint(p[4]);
                af[mt][3] = __float_as_uint(p[8 * SPITCH + 4]);
            }
#pragma unroll
            for (int nt = 0; nt < 4; nt++) {
                const float* p = Bsb + bBase + nt * (8 * SPITCH) + kb;
                bf[nt][0] = __float_as_uint(p[0]);
                bf[nt][1] = __float_as_uint(p[4]);
            }
#pragma unroll
            for (int mt = 0; mt < 4; mt++)
#pragma unroll
                for (int nt = 0; nt < 4; nt++)
                    mma_tf32(d[mt][nt], af[mt], bf[nt]);
        }
        __syncthreads();
    }
#undef ISSUE

    // ---- epilogue: cosine normalization + store ----
    const float* xn = g_xn + (b << 12);
    const float* yn = g_yn + (b << 12);
    float xv[4][2], yv[4][2];
#pragma unroll
    for (int mt = 0; mt < 4; mt++) {
        const int r = rowBase + wm * 64 + mt * 16 + g;
        xv[mt][0] = xn[r];
        xv[mt][1] = xn[r + 8];
    }
#pragma unroll
    for (int nt = 0; nt < 4; nt++) {
        const int cc = colBase + wn * 32 + nt * 8 + 2 * c;
        yv[nt][0] = yn[cc];
        yv[nt][1] = yn[cc + 1];
    }
    float* Cb = g_cos + ((size_t)b << 24);
#pragma unroll
    for (int mt = 0; mt < 4; mt++) {
        const int r = rowBase + wm * 64 + mt * 16 + g;
#pragma unroll
        for (int nt = 0; nt < 4; nt++) {
            const int cc = colBase + wn * 32 + nt * 8 + 2 * c;
            float2 o0, o1;
            o0.x = d[mt][nt][0] / (xv[mt][0] * yv[nt][0] + EPS1);
            o0.y = d[mt][nt][1] / (xv[mt][0] * yv[nt][1] + EPS1);
            o1.x = d[mt][nt][2] / (xv[mt][1] * yv[nt][0] + EPS1);
            o1.y = d[mt][nt][3] / (xv[mt][1] * yv[nt][1] + EPS1);
            *(float2*)(Cb + (size_t)r * Nn + cc) = o0;
            *(float2*)(Cb + (size_t)(r + 8) * Nn + cc) = o1;
        }
    }
}

// ---------------- 6. row pass: rowmax(cos), softmax denom --------------------
__global__ void __launch_bounds__(256) rowpass_kernel() {
    const int r = blockIdx.x;  // b*Nn + x
    const float* row = g_cos + (size_t)r * Nn;
    __shared__ float sh[Nn];
    __shared__ float red[256];
    const int tid = threadIdx.x;
    float m = -1e30f;
#pragma unroll
    for (int j = 0; j < 16; j++) {
        float v = row[tid + (j << 8)];
        sh[tid + (j << 8)] = v;
        m = fmaxf(m, v);
    }
    red[tid] = m;
    __syncthreads();
    for (int st = 128; st > 0; st >>= 1) {
        if (tid < st) red[tid] = fmaxf(red[tid], red[tid + st]);
        __syncthreads();
    }
    const float cmax = red[0];
    __syncthreads();
    const float s = 1.f / (1.f - cmax + EPS2);
    const float a = 1.f - s;
    float sum = 0.f;
#pragma unroll
    for (int j = 0; j < 16; j++) sum += __expf(fmaf(sh[tid + (j << 8)], s, a));
    red[tid] = sum;
    __syncthreads();
    for (int st = 128; st > 0; st >>= 1) {
        if (tid < st) red[tid] += red[tid + st];
        __syncthreads();
    }
    if (tid == 0) {
        g_pS[r] = s;
        g_pA[r] = a - logf(red[0]);
    }
}

// ---------------- 7. column pass: partial max over x (log-domain) ------------
__global__ void __launch_bounds__(256) colpass_kernel() {
    const int y = (blockIdx.x << 8) + threadIdx.x;
    const int chunk = blockIdx.y;
    const int b = blockIdx.z;
    __shared__ float ss[512], sa[512];
    const int r0 = (b << 12) + (chunk << 9);
    for (int i = threadIdx.x; i < 512; i += 256) {
        ss[i] = g_pS[r0 + i];
        sa[i] = g_pA[r0 + i];
    }
    __syncthreads();
    const float* base = g_cos + ((size_t)b << 24) + ((size_t)chunk << 21) + y;
    float m = -1e30f;
#pragma unroll 8
    for (int x = 0; x < 512; x++) {
        m = fmaxf(m, fmaf(base[(size_t)x << 12], ss[x], sa[x]));
    }
    g_cmax[(chunk << 14) + (b << 12) + y] = m;
}

// ---------------- 8. final: CS, MSEs, loss -----------------------------------
__global__ void __launch_bounds__(256) final_kernel(float* __restrict__ out) {
    const int tid = threadIdx.x;
    double cs = 0.0;
    for (int i = tid; i < Bn * Nn; i += 256) {
        float m = -1e30f;
#pragma unroll
        for (int ch = 0; ch < 8; ch++) m = fmaxf(m, g_cmax[(ch << 14) + i]);
        cs += exp((double)m);
    }
    double m1 = 0.0, m2 = 0.0;
    for (int i = tid; i < 512; i += 256) {
        m1 += g_msep[0][i];
        m2 += g_msep[1][i];
    }
    __shared__ double sh[3][256];
    sh[0][tid] = cs; sh[1][tid] = m1; sh[2][tid] = m2;
    __syncthreads();
    for (int st = 128; st > 0; st >>= 1) {
        if (tid < st) {
            sh[0][tid] += sh[0][tid + st];
            sh[1][tid] += sh[1][tid + st];
            sh[2][tid] += sh[2][tid + st];
        }
        __syncthreads();
    }
    if (tid == 0) {
        double CS = sh[0][0] / (double)(Bn * Nn);
        double mse1 = sh[1][0] / (double)IMG_ELEMS;
        double perc = sh[2][0] / (double)FEAT_ELEMS;
        out[0] = (float)(mse1 - log(CS) + 0.02 * perc);
    }
}

// ---------------- launch ------------------------------------------------------
extern "C" void kernel_launch(void* const* d_in, const int* in_sizes, int n_in,
                              void* d_out, int out_size) {
    const float* outputs = (const float*)d_in[0];
    const float* targets = (const float*)d_in[1];
    const float* of = (const float*)d_in[2];
    const float* tf = (const float*)d_in[3];
    float* out = (float*)d_out;

    const int gemm_smem = 4 * ABUF * 4;  // 73728 bytes
    cudaFuncSetAttribute(gemm_mma_kernel,
                         cudaFuncAttributeMaxDynamicSharedMemorySize, gemm_smem);

    mse_kernel<<<dim3(512, 2), 256>>>(outputs, targets, of, tf);
    mean_kernel<<<dim3(Bn * Cn, 2), 256>>>(of, tf);
    transpose_kernel<<<dim3(Nn / 32, Cn / 32, 2 * Bn), dim3(32, 8)>>>(of, tf);
    norm_kernel<<<dim3(Bn * Nn / 8, 2), 256>>>();
    gemm_mma_kernel<<<dim3(Nn / 128, Nn / 128, Bn), 256, gemm_smem>>>();
    rowpass_kernel<<<Bn * Nn, 256>>>();
    colpass_kernel<<<dim3(Nn / 256, 8, Bn), 256>>>();
    final_kernel<<<1, 256>>>(out);
}

// round 13
// speedup vs baseline: 3.1898x; 1.5562x over previous
#include <cuda_runtime.h>
#include <cuda_bf16.h>
#include <math.h>
#include <cstdint>

// Problem constants
//   outputs/targets:           [4, 3, 256, 256]  -> 786432 floats
//   output/target features:    [4, 256, 64, 64]  -> B=4, C=256, N=4096
#define Bn   4
#define Cn   256
#define Nn   4096
#define IMG_ELEMS  786432
#define FEAT_ELEMS 4194304
#define EPS1 1e-8f
#define EPS2 1e-5f

// ---------------- device scratch (allocation-free: static globals) ----------
static __device__ __nv_bfloat16 g_Xh[Bn * Nn * Cn];   // centered out-feats [b][n][c] bf16
static __device__ __nv_bfloat16 g_Yh[Bn * Nn * Cn];   // centered tgt-feats [b][n][c] bf16
static __device__ float  g_mean[2][Bn * Cn];          // per-(b,c) means
static __device__ float  g_xn[Bn * Nn];               // row norms of X (fp32)
static __device__ float  g_yn[Bn * Nn];               // row norms of Y (fp32)
static __device__ __nv_bfloat16 g_cosh[(size_t)Bn * Nn * Nn]; // 128 MB cosine [b][x][y]
static __device__ float  g_pS[Bn * Nn];               // per-row scale s = 1/(dmin+eps2)
static __device__ float  g_pA[Bn * Nn];               // per-row affine (1-s)-log(rowsum)
static __device__ float  g_cmax[8 * Bn * Nn];         // partial col maxima (8 x-chunks)
static __device__ double g_msep[2][512];              // MSE block partials

// ---------------- helpers ----------------------------------------------------
__device__ __forceinline__ uint32_t smem_u32(const void* p) {
    uint32_t a;
    asm("{ .reg .u64 t; cvta.to.shared.u64 t, %1; cvt.u32.u64 %0, t; }"
        : "=r"(a) : "l"(p));
    return a;
}
#define CP_ASYNC16(dst, src) \
    asm volatile("cp.async.cg.shared.global [%0], [%1], 16;" \
                 :: "r"(dst), "l"(src) : "memory")
#define CP_COMMIT() asm volatile("cp.async.commit_group;" ::: "memory")
#define CP_WAIT(n)  asm volatile("cp.async.wait_group %0;" :: "n"(n) : "memory")

__device__ __forceinline__ float2 bf2f(uint32_t u) {
    __nv_bfloat162 h;
    *reinterpret_cast<uint32_t*>(&h) = u;
    return __bfloat1622float2(h);
}

// warp-level bf16 MMA: D(16x8,f32) += A(16x16) * B(16x8), A row-major, B col-major
__device__ __forceinline__ void mma_bf16(float* d, const uint32_t* a,
                                         const uint32_t* b) {
    asm volatile(
        "mma.sync.aligned.m16n8k16.row.col.f32.bf16.bf16.f32 "
        "{%0,%1,%2,%3}, {%4,%5,%6,%7}, {%8,%9}, {%0,%1,%2,%3};"
        : "+f"(d[0]), "+f"(d[1]), "+f"(d[2]), "+f"(d[3])
        : "r"(a[0]), "r"(a[1]), "r"(a[2]), "r"(a[3]), "r"(b[0]), "r"(b[1]));
}

// ---------------- 1. MSE partials (deterministic two-stage) ------------------
__global__ void __launch_bounds__(256) mse_kernel(const float* __restrict__ o,
                                                  const float* __restrict__ t,
                                                  const float* __restrict__ of,
                                                  const float* __restrict__ tf) {
    const int which = blockIdx.y;
    const float* a = which ? of : o;
    const float* c = which ? tf : t;
    const int n = which ? FEAT_ELEMS : IMG_ELEMS;
    double s = 0.0;
    for (int i = blockIdx.x * 256 + threadIdx.x; i < n; i += 512 * 256) {
        float d = a[i] - c[i];
        s += (double)d * (double)d;
    }
    __shared__ double sh[256];
    sh[threadIdx.x] = s;
    __syncthreads();
    for (int st = 128; st > 0; st >>= 1) {
        if (threadIdx.x < st) sh[threadIdx.x] += sh[threadIdx.x + st];
        __syncthreads();
    }
    if (threadIdx.x == 0) g_msep[which][blockIdx.x] = sh[0];
}

// ---------------- 2. per-(b,c) means over N positions ------------------------
__global__ void __launch_bounds__(256) mean_kernel(const float* __restrict__ of,
                                                   const float* __restrict__ tf) {
    const float* src = blockIdx.y ? tf : of;
    const int bc = blockIdx.x;
    const float* p = src + (size_t)bc * Nn;
    float s = 0.f;
    for (int i = threadIdx.x; i < Nn; i += 256) s += p[i];
    __shared__ float sh[256];
    sh[threadIdx.x] = s;
    __syncthreads();
    for (int st = 128; st > 0; st >>= 1) {
        if (threadIdx.x < st) sh[threadIdx.x] += sh[threadIdx.x + st];
        __syncthreads();
    }
    if (threadIdx.x == 0) g_mean[blockIdx.y][bc] = sh[0] * (1.f / Nn);
}

// ---------------- 3. transpose [C][N] -> [N][C], center, cast bf16 -----------
__global__ void __launch_bounds__(256) transpose_kernel(const float* __restrict__ of,
                                                        const float* __restrict__ tf) {
    const int tz = blockIdx.z;
    const int tensor = tz >> 2;
    const int b = tz & 3;
    const float* src = (tensor ? tf : of) + (size_t)b * Cn * Nn;
    __nv_bfloat16* dst = (tensor ? g_Yh : g_Xh) + (size_t)b * Nn * Cn;
    const float* mean = g_mean[tensor] + b * Cn;
    __shared__ float tile[32][33];
    const int tx = threadIdx.x, ty = threadIdx.y;  // 32 x 8
    const int n0 = blockIdx.x * 32, c0 = blockIdx.y * 32;
#pragma unroll
    for (int j = 0; j < 4; j++) {
        int c = c0 + ty + j * 8;
        tile[ty + j * 8][tx] = src[(size_t)c * Nn + n0 + tx] - mean[c];
    }
    __syncthreads();
#pragma unroll
    for (int j = 0; j < 4; j++) {
        int n = n0 + ty + j * 8;
        dst[(size_t)n * Cn + c0 + tx] = __float2bfloat16(tile[tx][ty + j * 8]);
    }
}

// ---------------- 4. per-row L2 norms (from bf16 rows) ------------------------
__global__ void __launch_bounds__(256) norm_kernel() {
    const int tensor = blockIdx.y;
    const __nv_bfloat16* X = tensor ? g_Yh : g_Xh;
    float* out = tensor ? g_yn : g_xn;
    const int warp = threadIdx.x >> 5, lane = threadIdx.x & 31;
    const int r = blockIdx.x * 8 + warp;
    const uint4* p = (const uint4*)(X + (size_t)r * Cn);
    uint4 q = p[lane];  // 8 bf16
    const uint32_t* w = (const uint32_t*)&q;
    float s = 0.f;
#pragma unroll
    for (int i = 0; i < 4; i++) {
        float2 f = bf2f(w[i]);
        s += f.x * f.x + f.y * f.y;
    }
    for (int o = 16; o; o >>= 1) s += __shfl_xor_sync(0xffffffffu, s, o);
    if (lane == 0) out[r] = sqrtf(s);
}

// ---------------- 5. bf16 mma.sync GEMM -> bf16 cosine matrix ----------------
// BM=128, BN=128, BK=32, 256 threads (8 warps, 2x4 grid, warp tile 64x32).
// Per warp: 4 m-tiles x 4 n-tiles of m16n8k16. cp.async double-buffered smem.
// Smem rows = 64 B (32 bf16); XOR swizzle on 16B groups: w ^= ((row>>1)&3)<<2
// -> all fragment LDS conflict-free, cp.async stays 16B-aligned.
__global__ void __launch_bounds__(256) gemm_mma_kernel() {
    __shared__ __align__(16) uint32_t smem[8192];  // [A0|A1|B0|B1] x 2048 words

    const int b = blockIdx.z;
    const int rowBase = blockIdx.y * 128, colBase = blockIdx.x * 128;
    const __nv_bfloat16* __restrict__ Xb = g_Xh + (size_t)b * (Nn * Cn);
    const __nv_bfloat16* __restrict__ Yb = g_Yh + (size_t)b * (Nn * Cn);
    const int tid = threadIdx.x;
    const int wid = tid >> 5, lane = tid & 31;
    const int wm = wid & 1, wn = wid >> 1;   // 2 along M, 4 along N
    const int g = lane >> 2, c = lane & 3;
    const int swc = ((g >> 1) & 3) << 2;

    // cp.async staging: 128 rows x 64 B per operand per chunk; 2 xfers/thread/op
    const int row0 = tid >> 2, tq = tid & 3;
    const __nv_bfloat16* Agp = Xb + (size_t)(rowBase + row0) * Cn + tq * 8;
    const __nv_bfloat16* Bgp = Yb + (size_t)(colBase + row0) * Cn + tq * 8;
    const uint32_t sbase = smem_u32(smem);
    const uint32_t soff = (uint32_t)(row0 * 64 + (tq ^ ((row0 >> 1) & 3)) * 16);

#define ISSUE(ch, buf) do {                                                   \
        const uint32_t dA = sbase + (buf) * 8192 + soff;                      \
        const uint32_t dB = sbase + 16384 + (buf) * 8192 + soff;              \
        CP_ASYNC16(dA,        Agp + (ch) * 32);                               \
        CP_ASYNC16(dA + 4096, Agp + 64 * Cn + (ch) * 32);                     \
        CP_ASYNC16(dB,        Bgp + (ch) * 32);                               \
        CP_ASYNC16(dB + 4096, Bgp + 64 * Cn + (ch) * 32);                     \
        CP_COMMIT();                                                          \
    } while (0)

    float d[4][4][4];
#pragma unroll
    for (int mt = 0; mt < 4; mt++)
#pragma unroll
        for (int nt = 0; nt < 4; nt++)
#pragma unroll
            for (int k = 0; k < 4; k++) d[mt][nt][k] = 0.f;

    ISSUE(0, 0);
    for (int ch = 0; ch < 8; ch++) {
        if (ch < 7) {
            ISSUE(ch + 1, (ch + 1) & 1);
            CP_WAIT(1);
        } else {
            CP_WAIT(0);
        }
        __syncthreads();

        const uint32_t* As = smem + (ch & 1) * 2048;
        const uint32_t* Bs = smem + 4096 + (ch & 1) * 2048;
#pragma unroll
        for (int kk = 0; kk < 2; kk++) {
            const int w0 = ((kk << 3) | c) ^ swc;
            const int w1 = w0 ^ 4;
            uint32_t af[4][4], bf[4][2];
#pragma unroll
            for (int mt = 0; mt < 4; mt++) {
                const uint32_t* p = As + (wm * 64 + mt * 16 + g) * 16;
                af[mt][0] = p[w0];
                af[mt][1] = p[128 + w0];
                af[mt][2] = p[w1];
                af[mt][3] = p[128 + w1];
            }
#pragma unroll
            for (int nt = 0; nt < 4; nt++) {
                const uint32_t* p = Bs + (wn * 32 + nt * 8 + g) * 16;
                bf[nt][0] = p[w0];
                bf[nt][1] = p[w1];
            }
#pragma unroll
            for (int mt = 0; mt < 4; mt++)
#pragma unroll
                for (int nt = 0; nt < 4; nt++)
                    mma_bf16(d[mt][nt], af[mt], bf[nt]);
        }
        __syncthreads();
    }
#undef ISSUE

    // ---- epilogue: cosine normalization + bf16 store ----
    const float* xn = g_xn + (b << 12);
    const float* yn = g_yn + (b << 12);
    float xv[4][2], yv[4][2];
#pragma unroll
    for (int mt = 0; mt < 4; mt++) {
        const int r = rowBase + wm * 64 + mt * 16 + g;
        xv[mt][0] = xn[r];
        xv[mt][1] = xn[r + 8];
    }
#pragma unroll
    for (int nt = 0; nt < 4; nt++) {
        const int cc = colBase + wn * 32 + nt * 8 + 2 * c;
        yv[nt][0] = yn[cc];
        yv[nt][1] = yn[cc + 1];
    }
    __nv_bfloat16* Cb = g_cosh + ((size_t)b << 24);
#pragma unroll
    for (int mt = 0; mt < 4; mt++) {
        const int r = rowBase + wm * 64 + mt * 16 + g;
#pragma unroll
        for (int nt = 0; nt < 4; nt++) {
            const int cc = colBase + wn * 32 + nt * 8 + 2 * c;
            __nv_bfloat162 o0 = __floats2bfloat162_rn(
                d[mt][nt][0] / (xv[mt][0] * yv[nt][0] + EPS1),
                d[mt][nt][1] / (xv[mt][0] * yv[nt][1] + EPS1));
            __nv_bfloat162 o1 = __floats2bfloat162_rn(
                d[mt][nt][2] / (xv[mt][1] * yv[nt][0] + EPS1),
                d[mt][nt][3] / (xv[mt][1] * yv[nt][1] + EPS1));
            *(__nv_bfloat162*)(Cb + (size_t)r * Nn + cc) = o0;
            *(__nv_bfloat162*)(Cb + (size_t)(r + 8) * Nn + cc) = o1;
        }
    }
}

// ---------------- 6. row pass: rowmax(cos), softmax denom --------------------
// d = 1-cos; s = 1/(dmin+eps2); w_y = exp((1-s) + cos_y*s)
__global__ void __launch_bounds__(256) rowpass_kernel() {
    const int r = blockIdx.x;  // b*Nn + x
    const uint4* row = (const uint4*)(g_cosh + (size_t)r * Nn);
    const int tid = threadIdx.x;
    uint4 q0 = row[tid];
    uint4 q1 = row[tid + 256];
    float v[16];
    {
        const uint32_t* w0 = (const uint32_t*)&q0;
        const uint32_t* w1 = (const uint32_t*)&q1;
#pragma unroll
        for (int i = 0; i < 4; i++) {
            float2 f = bf2f(w0[i]);
            v[2 * i] = f.x; v[2 * i + 1] = f.y;
            f = bf2f(w1[i]);
            v[8 + 2 * i] = f.x; v[9 + 2 * i] = f.y;
        }
    }
    __shared__ float red[256];
    float m = v[0];
#pragma unroll
    for (int i = 1; i < 16; i++) m = fmaxf(m, v[i]);
    red[tid] = m;
    __syncthreads();
    for (int st = 128; st > 0; st >>= 1) {
        if (tid < st) red[tid] = fmaxf(red[tid], red[tid + st]);
        __syncthreads();
    }
    const float cmax = red[0];
    __syncthreads();
    const float s = 1.f / (1.f - cmax + EPS2);
    const float a = 1.f - s;
    float sum = 0.f;
#pragma unroll
    for (int i = 0; i < 16; i++) sum += __expf(fmaf(v[i], s, a));
    red[tid] = sum;
    __syncthreads();
    for (int st = 128; st > 0; st >>= 1) {
        if (tid < st) red[tid] += red[tid + st];
        __syncthreads();
    }
    if (tid == 0) {
        g_pS[r] = s;
        g_pA[r] = a - logf(red[0]);
    }
}

// ---------------- 7. column pass: partial max over x (log-domain) ------------
// log c[x][y] = cos*s_x + A_x -> max over 512-row x-chunk, 2 y per thread
__global__ void __launch_bounds__(256) colpass_kernel() {
    const int tid = threadIdx.x;
    const int ypair = blockIdx.x * 256 + tid;  // 0..2047 (y = 2*ypair)
    const int chunk = blockIdx.y;              // 0..7
    const int b = blockIdx.z;                  // 0..3
    __shared__ float ss[512], sa[512];
    const int r0 = (b << 12) + (chunk << 9);
    for (int i = tid; i < 512; i += 256) {
        ss[i] = g_pS[r0 + i];
        sa[i] = g_pA[r0 + i];
    }
    __syncthreads();
    const uint32_t* base =
        (const uint32_t*)(g_cosh + ((size_t)b << 24) + ((size_t)chunk << 21)) + ypair;
    float m0 = -1e30f, m1 = -1e30f;
#pragma unroll 8
    for (int x = 0; x < 512; x++) {
        float2 f = bf2f(base[(size_t)x << 11]);
        m0 = fmaxf(m0, fmaf(f.x, ss[x], sa[x]));
        m1 = fmaxf(m1, fmaf(f.y, ss[x], sa[x]));
    }
    const int y = ypair * 2;
    g_cmax[(chunk << 14) + (b << 12) + y] = m0;
    g_cmax[(chunk << 14) + (b << 12) + y + 1] = m1;
}

// ---------------- 8. final: CS, MSEs, loss -----------------------------------
__global__ void __launch_bounds__(256) final_kernel(float* __restrict__ out) {
    const int tid = threadIdx.x;
    double cs = 0.0;
    for (int i = tid; i < Bn * Nn; i += 256) {
        float m = -1e30f;
#pragma unroll
        for (int ch = 0; ch < 8; ch++) m = fmaxf(m, g_cmax[(ch << 14) + i]);
        cs += exp((double)m);
    }
    double m1 = 0.0, m2 = 0.0;
    for (int i = tid; i < 512; i += 256) {
        m1 += g_msep[0][i];
        m2 += g_msep[1][i];
    }
    __shared__ double sh[3][256];
    sh[0][tid] = cs; sh[1][tid] = m1; sh[2][tid] = m2;
    __syncthreads();
    for (int st = 128; st > 0; st >>= 1) {
        if (tid < st) {
            sh[0][tid] += sh[0][tid + st];
            sh[1][tid] += sh[1][tid + st];
            sh[2][tid] += sh[2][tid + st];
        }
        __syncthreads();
    }
    if (tid == 0) {
        double CS = sh[0][0] / (double)(Bn * Nn);
        double mse1 = sh[1][0] / (double)IMG_ELEMS;
        double perc = sh[2][0] / (double)FEAT_ELEMS;
        out[0] = (float)(mse1 - log(CS) + 0.02 * perc);
    }
}

// ---------------- launch ------------------------------------------------------
extern "C" void kernel_launch(void* const* d_in, const int* in_sizes, int n_in,
                              void* d_out, int out_size) {
    const float* outputs = (const float*)d_in[0];
    const float* targets = (const float*)d_in[1];
    const float* of = (const float*)d_in[2];
    const float* tf = (const float*)d_in[3];
    float* out = (float*)d_out;

    mse_kernel<<<dim3(512, 2), 256>>>(outputs, targets, of, tf);
    mean_kernel<<<dim3(Bn * Cn, 2), 256>>>(of, tf);
    transpose_kernel<<<dim3(Nn / 32, Cn / 32, 2 * Bn), dim3(32, 8)>>>(of, tf);
    norm_kernel<<<dim3(Bn * Nn / 8, 2), 256>>>();
    gemm_mma_kernel<<<dim3(Nn / 128, Nn / 128, Bn), 256>>>();
    rowpass_kernel<<<Bn * Nn, 256>>>();
    colpass_kernel<<<dim3(Nn / 512, 8, Bn), 256>>>();
    final_kernel<<<1, 256>>>(out);
}

// round 14
// speedup vs baseline: 3.2795x; 1.0281x over previous
#include <cuda_runtime.h>
#include <cuda_bf16.h>
#include <math.h>
#include <cstdint>

// Problem constants
//   outputs/targets:           [4, 3, 256, 256]  -> 786432 floats
//   output/target features:    [4, 256, 64, 64]  -> B=4, C=256, N=4096
#define Bn   4
#define Cn   256
#define Nn   4096
#define IMG_ELEMS  786432
#define FEAT_ELEMS 4194304
#define EPS1 1e-8f
#define EPS2 1e-5f

// ---------------- device scratch (allocation-free: static globals) ----------
static __device__ __nv_bfloat16 g_Xh[Bn * Nn * Cn];   // centered out-feats [b][n][c] bf16
static __device__ __nv_bfloat16 g_Yh[Bn * Nn * Cn];   // centered tgt-feats [b][n][c] bf16
static __device__ float  g_mean[2][Bn * Cn];          // per-(b,c) means
static __device__ float  g_xn[Bn * Nn];               // row norms of X (fp32)
static __device__ float  g_yn[Bn * Nn];               // row norms of Y (fp32)
static __device__ __nv_bfloat16 g_cosh[(size_t)Bn * Nn * Nn]; // 128 MB cosine [b][x][y]
static __device__ float  g_pS[Bn * Nn];               // per-row scale s = 1/(dmin+eps2)
static __device__ float  g_pA[Bn * Nn];               // per-row affine (1-s)-log(rowsum)
static __device__ float  g_cmax[8 * Bn * Nn];         // partial col maxima (8 x-chunks)
static __device__ double g_msep[2][512];              // MSE block partials

// ---------------- helpers ----------------------------------------------------
__device__ __forceinline__ uint32_t smem_u32(const void* p) {
    uint32_t a;
    asm("{ .reg .u64 t; cvta.to.shared.u64 t, %1; cvt.u32.u64 %0, t; }"
        : "=r"(a) : "l"(p));
    return a;
}
#define CP_ASYNC16(dst, src) \
    asm volatile("cp.async.cg.shared.global [%0], [%1], 16;" \
                 :: "r"(dst), "l"(src) : "memory")
#define CP_COMMIT() asm volatile("cp.async.commit_group;" ::: "memory")
#define CP_WAIT(n)  asm volatile("cp.async.wait_group %0;" :: "n"(n) : "memory")

__device__ __forceinline__ float2 bf2f(uint32_t u) {
    __nv_bfloat162 h;
    *reinterpret_cast<uint32_t*>(&h) = u;
    return __bfloat1622float2(h);
}

// ldmatrix x4: four 8x8 b16 tiles, addresses supplied per-lane
__device__ __forceinline__ void ldmx4(uint32_t* r, uint32_t addr) {
    asm volatile(
        "ldmatrix.sync.aligned.m8n8.x4.shared.b16 {%0,%1,%2,%3}, [%4];"
        : "=r"(r[0]), "=r"(r[1]), "=r"(r[2]), "=r"(r[3]) : "r"(addr));
}

// warp-level bf16 MMA: D(16x8,f32) += A(16x16) * B(16x8)
__device__ __forceinline__ void mma_bf16(float* d, const uint32_t* a,
                                         uint32_t b0, uint32_t b1) {
    asm volatile(
        "mma.sync.aligned.m16n8k16.row.col.f32.bf16.bf16.f32 "
        "{%0,%1,%2,%3}, {%4,%5,%6,%7}, {%8,%9}, {%0,%1,%2,%3};"
        : "+f"(d[0]), "+f"(d[1]), "+f"(d[2]), "+f"(d[3])
        : "r"(a[0]), "r"(a[1]), "r"(a[2]), "r"(a[3]), "r"(b0), "r"(b1));
}

// ---------------- 1. MSE partials (deterministic two-stage) ------------------
__global__ void __launch_bounds__(256) mse_kernel(const float* __restrict__ o,
                                                  const float* __restrict__ t,
                                                  const float* __restrict__ of,
                                                  const float* __restrict__ tf) {
    const int which = blockIdx.y;
    const float* a = which ? of : o;
    const float* c = which ? tf : t;
    const int n = which ? FEAT_ELEMS : IMG_ELEMS;
    double s = 0.0;
    for (int i = blockIdx.x * 256 + threadIdx.x; i < n; i += 512 * 256) {
        float d = a[i] - c[i];
        s += (double)d * (double)d;
    }
    __shared__ double sh[256];
    sh[threadIdx.x] = s;
    __syncthreads();
    for (int st = 128; st > 0; st >>= 1) {
        if (threadIdx.x < st) sh[threadIdx.x] += sh[threadIdx.x + st];
        __syncthreads();
    }
    if (threadIdx.x == 0) g_msep[which][blockIdx.x] = sh[0];
}

// ---------------- 2. per-(b,c) means over N positions ------------------------
__global__ void __launch_bounds__(256) mean_kernel(const float* __restrict__ of,
                                                   const float* __restrict__ tf) {
    const float* src = blockIdx.y ? tf : of;
    const int bc = blockIdx.x;
    const float* p = src + (size_t)bc * Nn;
    float s = 0.f;
    for (int i = threadIdx.x; i < Nn; i += 256) s += p[i];
    __shared__ float sh[256];
    sh[threadIdx.x] = s;
    __syncthreads();
    for (int st = 128; st > 0; st >>= 1) {
        if (threadIdx.x < st) sh[threadIdx.x] += sh[threadIdx.x + st];
        __syncthreads();
    }
    if (threadIdx.x == 0) g_mean[blockIdx.y][bc] = sh[0] * (1.f / Nn);
}

// ---------------- 3. transpose [C][N] -> [N][C], center, cast bf16 -----------
__global__ void __launch_bounds__(256) transpose_kernel(const float* __restrict__ of,
                                                        const float* __restrict__ tf) {
    const int tz = blockIdx.z;
    const int tensor = tz >> 2;
    const int b = tz & 3;
    const float* src = (tensor ? tf : of) + (size_t)b * Cn * Nn;
    __nv_bfloat16* dst = (tensor ? g_Yh : g_Xh) + (size_t)b * Nn * Cn;
    const float* mean = g_mean[tensor] + b * Cn;
    __shared__ float tile[32][33];
    const int tx = threadIdx.x, ty = threadIdx.y;  // 32 x 8
    const int n0 = blockIdx.x * 32, c0 = blockIdx.y * 32;
#pragma unroll
    for (int j = 0; j < 4; j++) {
        int c = c0 + ty + j * 8;
        tile[ty + j * 8][tx] = src[(size_t)c * Nn + n0 + tx] - mean[c];
    }
    __syncthreads();
#pragma unroll
    for (int j = 0; j < 4; j++) {
        int n = n0 + ty + j * 8;
        dst[(size_t)n * Cn + c0 + tx] = __float2bfloat16(tile[tx][ty + j * 8]);
    }
}

// ---------------- 4. per-row L2 norms (from bf16 rows) ------------------------
__global__ void __launch_bounds__(256) norm_kernel() {
    const int tensor = blockIdx.y;
    const __nv_bfloat16* X = tensor ? g_Yh : g_Xh;
    float* out = tensor ? g_yn : g_xn;
    const int warp = threadIdx.x >> 5, lane = threadIdx.x & 31;
    const int r = blockIdx.x * 8 + warp;
    const uint4* p = (const uint4*)(X + (size_t)r * Cn);
    uint4 q = p[lane];  // 8 bf16
    const uint32_t* w = (const uint32_t*)&q;
    float s = 0.f;
#pragma unroll
    for (int i = 0; i < 4; i++) {
        float2 f = bf2f(w[i]);
        s += f.x * f.x + f.y * f.y;
    }
    for (int o = 16; o; o >>= 1) s += __shfl_xor_sync(0xffffffffu, s, o);
    if (lane == 0) out[r] = sqrtf(s);
}

// ---------------- 5. bf16 mma.sync GEMM -> bf16 cosine matrix ----------------
// BM=128, BN=128, BK=32, 256 threads (8 warps, 2x4 grid, warp tile 64x32).
// Fragment loads via ldmatrix.x4 (6 per k-step vs 24 LDS.32).
// Smem rows = 64 B; XOR swizzle on 16B groups: grp ^= (row>>1)&3 ->
// ldmatrix phases and cp.async stores both conflict-free.
__global__ void __launch_bounds__(256) gemm_mma_kernel() {
    __shared__ __align__(16) uint32_t smem[8192];  // [A0|A1|B0|B1] x 2048 words

    const int b = blockIdx.z;
    const int rowBase = blockIdx.y * 128, colBase = blockIdx.x * 128;
    const __nv_bfloat16* __restrict__ Xb = g_Xh + (size_t)b * (Nn * Cn);
    const __nv_bfloat16* __restrict__ Yb = g_Yh + (size_t)b * (Nn * Cn);
    const int tid = threadIdx.x;
    const int wid = tid >> 5, lane = tid & 31;
    const int wm = wid & 1, wn = wid >> 1;   // 2 along M, 4 along N
    const int g = lane >> 2, c = lane & 3;

    // cp.async staging: 128 rows x 64 B per operand per chunk; 2 xfers/thread/op
    const int row0 = tid >> 2, tq = tid & 3;
    const __nv_bfloat16* Agp = Xb + (size_t)(rowBase + row0) * Cn + tq * 8;
    const __nv_bfloat16* Bgp = Yb + (size_t)(colBase + row0) * Cn + tq * 8;
    const uint32_t sbase = smem_u32(smem);
    const uint32_t soff = (uint32_t)(row0 * 64 + (tq ^ ((row0 >> 1) & 3)) * 16);

#define ISSUE(ch, buf) do {                                                   \
        const uint32_t dA = sbase + (buf) * 8192 + soff;                      \
        const uint32_t dB = sbase + 16384 + (buf) * 8192 + soff;              \
        CP_ASYNC16(dA,        Agp + (ch) * 32);                               \
        CP_ASYNC16(dA + 4096, Agp + 64 * Cn + (ch) * 32);                     \
        CP_ASYNC16(dB,        Bgp + (ch) * 32);                               \
        CP_ASYNC16(dB + 4096, Bgp + 64 * Cn + (ch) * 32);                     \
        CP_COMMIT();                                                          \
    } while (0)

    float d[4][4][4];
#pragma unroll
    for (int mt = 0; mt < 4; mt++)
#pragma unroll
        for (int nt = 0; nt < 4; nt++)
#pragma unroll
            for (int k = 0; k < 4; k++) d[mt][nt][k] = 0.f;

    // ldmatrix per-lane address geometry
    const int arow = wm * 64 + (lane & 15);        // + mt*16
    const int ahi = lane >> 4;                     // k-halfgroup select
    const uint32_t asw = (uint32_t)((arow >> 1) & 3);
    const uint32_t aoff = (uint32_t)(arow * 64);
    const int brow = wn * 32 + lane;               // covers 4 n-tiles of 8 rows
    const uint32_t bsw = (uint32_t)((brow >> 1) & 3);
    const uint32_t boff = 16384u + (uint32_t)(brow * 64);

    ISSUE(0, 0);
    for (int ch = 0; ch < 8; ch++) {
        if (ch < 7) {
            ISSUE(ch + 1, (ch + 1) & 1);
            CP_WAIT(1);
        } else {
            CP_WAIT(0);
        }
        __syncthreads();

        const uint32_t bufb = (uint32_t)((ch & 1) * 8192);
        const uint32_t abase = sbase + bufb + aoff;
        const uint32_t bbase = sbase + bufb + boff;
#pragma unroll
        for (int kk = 0; kk < 2; kk++) {
            uint32_t af[4][4], b0[4], b1[4];
            const uint32_t akg = (uint32_t)(kk * 2 + ahi);
#pragma unroll
            for (int mt = 0; mt < 4; mt++)
                ldmx4(af[mt], abase + (uint32_t)(mt * 1024) + ((akg ^ asw) << 4));
            ldmx4(b0, bbase + (((uint32_t)(kk * 2) ^ bsw) << 4));
            ldmx4(b1, bbase + (((uint32_t)(kk * 2 + 1) ^ bsw) << 4));
#pragma unroll
            for (int mt = 0; mt < 4; mt++)
#pragma unroll
                for (int nt = 0; nt < 4; nt++)
                    mma_bf16(d[mt][nt], af[mt], b0[nt], b1[nt]);
        }
        __syncthreads();
    }
#undef ISSUE

    // ---- epilogue: cosine normalization + bf16 store ----
    const float* xn = g_xn + (b << 12);
    const float* yn = g_yn + (b << 12);
    float xv[4][2], yv[4][2];
#pragma unroll
    for (int mt = 0; mt < 4; mt++) {
        const int r = rowBase + wm * 64 + mt * 16 + g;
        xv[mt][0] = xn[r];
        xv[mt][1] = xn[r + 8];
    }
#pragma unroll
    for (int nt = 0; nt < 4; nt++) {
        const int cc = colBase + wn * 32 + nt * 8 + 2 * c;
        yv[nt][0] = yn[cc];
        yv[nt][1] = yn[cc + 1];
    }
    __nv_bfloat16* Cb = g_cosh + ((size_t)b << 24);
#pragma unroll
    for (int mt = 0; mt < 4; mt++) {
        const int r = rowBase + wm * 64 + mt * 16 + g;
#pragma unroll
        for (int nt = 0; nt < 4; nt++) {
            const int cc = colBase + wn * 32 + nt * 8 + 2 * c;
            __nv_bfloat162 o0 = __floats2bfloat162_rn(
                d[mt][nt][0] / (xv[mt][0] * yv[nt][0] + EPS1),
                d[mt][nt][1] / (xv[mt][0] * yv[nt][1] + EPS1));
            __nv_bfloat162 o1 = __floats2bfloat162_rn(
                d[mt][nt][2] / (xv[mt][1] * yv[nt][0] + EPS1),
                d[mt][nt][3] / (xv[mt][1] * yv[nt][1] + EPS1));
            *(__nv_bfloat162*)(Cb + (size_t)r * Nn + cc) = o0;
            *(__nv_bfloat162*)(Cb + (size_t)(r + 8) * Nn + cc) = o1;
        }
    }
}

// ---------------- 6. row pass: rowmax(cos), softmax denom --------------------
// d = 1-cos; s = 1/(dmin+eps2); w_y = exp((1-s) + cos_y*s)
__global__ void __launch_bounds__(256) rowpass_kernel() {
    const int r = blockIdx.x;  // b*Nn + x
    const uint4* row = (const uint4*)(g_cosh + (size_t)r * Nn);
    const int tid = threadIdx.x;
    uint4 q0 = row[tid];
    uint4 q1 = row[tid + 256];
    float v[16];
    {
        const uint32_t* w0 = (const uint32_t*)&q0;
        const uint32_t* w1 = (const uint32_t*)&q1;
#pragma unroll
        for (int i = 0; i < 4; i++) {
            float2 f = bf2f(w0[i]);
            v[2 * i] = f.x; v[2 * i + 1] = f.y;
            f = bf2f(w1[i]);
            v[8 + 2 * i] = f.x; v[9 + 2 * i] = f.y;
        }
    }
    __shared__ float red[256];
    float m = v[0];
#pragma unroll
    for (int i = 1; i < 16; i++) m = fmaxf(m, v[i]);
    red[tid] = m;
    __syncthreads();
    for (int st = 128; st > 0; st >>= 1) {
        if (tid < st) red[tid] = fmaxf(red[tid], red[tid + st]);
        __syncthreads();
    }
    const float cmax = red[0];
    __syncthreads();
    const float s = 1.f / (1.f - cmax + EPS2);
    const float a = 1.f - s;
    float sum = 0.f;
#pragma unroll
    for (int i = 0; i < 16; i++) sum += __expf(fmaf(v[i], s, a));
    red[tid] = sum;
    __syncthreads();
    for (int st = 128; st > 0; st >>= 1) {
        if (tid < st) red[tid] += red[tid + st];
        __syncthreads();
    }
    if (tid == 0) {
        g_pS[r] = s;
        g_pA[r] = a - logf(red[0]);
    }
}

// ---------------- 7. column pass: partial max over x (log-domain) ------------
// log c[x][y] = cos*s_x + A_x -> max over 512-row x-chunk, 2 y per thread
__global__ void __launch_bounds__(256) colpass_kernel() {
    const int tid = threadIdx.x;
    const int ypair = blockIdx.x * 256 + tid;  // 0..2047 (y = 2*ypair)
    const int chunk = blockIdx.y;              // 0..7
    const int b = blockIdx.z;                  // 0..3
    __shared__ float ss[512], sa[512];
    const int r0 = (b << 12) + (chunk << 9);
    for (int i = tid; i < 512; i += 256) {
        ss[i] = g_pS[r0 + i];
        sa[i] = g_pA[r0 + i];
    }
    __syncthreads();
    const uint32_t* base =
        (const uint32_t*)(g_cosh + ((size_t)b << 24) + ((size_t)chunk << 21)) + ypair;
    float m0 = -1e30f, m1 = -1e30f;
#pragma unroll 8
    for (int x = 0; x < 512; x++) {
        float2 f = bf2f(base[(size_t)x << 11]);
        m0 = fmaxf(m0, fmaf(f.x, ss[x], sa[x]));
        m1 = fmaxf(m1, fmaf(f.y, ss[x], sa[x]));
    }
    const int y = ypair * 2;
    g_cmax[(chunk << 14) + (b << 12) + y] = m0;
    g_cmax[(chunk << 14) + (b << 12) + y + 1] = m1;
}

// ---------------- 8. final: CS, MSEs, loss -----------------------------------
__global__ void __launch_bounds__(256) final_kernel(float* __restrict__ out) {
    const int tid = threadIdx.x;
    double cs = 0.0;
    for (int i = tid; i < Bn * Nn; i += 256) {
        float m = -1e30f;
#pragma unroll
        for (int ch = 0; ch < 8; ch++) m = fmaxf(m, g_cmax[(ch << 14) + i]);
        cs += exp((double)m);
    }
    double m1 = 0.0, m2 = 0.0;
    for (int i = tid; i < 512; i += 256) {
        m1 += g_msep[0][i];
        m2 += g_msep[1][i];
    }
    __shared__ double sh[3][256];
    sh[0][tid] = cs; sh[1][tid] = m1; sh[2][tid] = m2;
    __syncthreads();
    for (int st = 128; st > 0; st >>= 1) {
        if (tid < st) {
            sh[0][tid] += sh[0][tid + st];
            sh[1][tid] += sh[1][tid + st];
            sh[2][tid] += sh[2][tid + st];
        }
        __syncthreads();
    }
    if (tid == 0) {
        double CS = sh[0][0] / (double)(Bn * Nn);
        double mse1 = sh[1][0] / (double)IMG_ELEMS;
        double perc = sh[2][0] / (double)FEAT_ELEMS;
        out[0] = (float)(mse1 - log(CS) + 0.02 * perc);
    }
}

// ---------------- launch ------------------------------------------------------
extern "C" void kernel_launch(void* const* d_in, const int* in_sizes, int n_in,
                              void* d_out, int out_size) {
    const float* outputs = (const float*)d_in[0];
    const float* targets = (const float*)d_in[1];
    const float* of = (const float*)d_in[2];
    const float* tf = (const float*)d_in[3];
    float* out = (float*)d_out;

    mse_kernel<<<dim3(512, 2), 256>>>(outputs, targets, of, tf);
    mean_kernel<<<dim3(Bn * Cn, 2), 256>>>(of, tf);
    transpose_kernel<<<dim3(Nn / 32, Cn / 32, 2 * Bn), dim3(32, 8)>>>(of, tf);
    norm_kernel<<<dim3(Bn * Nn / 8, 2), 256>>>();
    gemm_mma_kernel<<<dim3(Nn / 128, Nn / 128, Bn), 256>>>();
    rowpass_kernel<<<Bn * Nn, 256>>>();
    colpass_kernel<<<dim3(Nn / 512, 8, Bn), 256>>>();
    final_kernel<<<1, 256>>>(out);
}

// round 15
// speedup vs baseline: 3.3214x; 1.0128x over previous
#include <cuda_runtime.h>
#include <cuda_bf16.h>
#include <math.h>
#include <cstdint>

// Problem constants
//   outputs/targets:           [4, 3, 256, 256]  -> 786432 floats
//   output/target features:    [4, 256, 64, 64]  -> B=4, C=256, N=4096
#define Bn   4
#define Cn   256
#define Nn   4096
#define IMG_ELEMS  786432
#define FEAT_ELEMS 4194304
#define EPS1 1e-8f
#define EPS2 1e-5f

// ---------------- device scratch (allocation-free: static globals) ----------
static __device__ __nv_bfloat16 g_Xh[Bn * Nn * Cn];   // centered out-feats [b][n][c] bf16
static __device__ __nv_bfloat16 g_Yh[Bn * Nn * Cn];   // centered tgt-feats [b][n][c] bf16
static __device__ float  g_mean[2][Bn * Cn];          // per-(b,c) means
static __device__ float  g_xn[Bn * Nn];               // row norms of X (fp32)
static __device__ float  g_yn[Bn * Nn];               // row norms of Y (fp32)
static __device__ __nv_bfloat16 g_cosh[(size_t)Bn * Nn * Nn]; // 128 MB cosine [b][x][y]
static __device__ float  g_pS[Bn * Nn];               // per-row scale s = 1/(dmin+eps2)
static __device__ float  g_pA[Bn * Nn];               // per-row affine (1-s)-log(rowsum)
static __device__ float  g_cmax[8 * Bn * Nn];         // partial col maxima (8 x-chunks)
static __device__ double g_msep[2][512];              // MSE block partials

// ---------------- helpers ----------------------------------------------------
__device__ __forceinline__ uint32_t smem_u32(const void* p) {
    uint32_t a;
    asm("{ .reg .u64 t; cvta.to.shared.u64 t, %1; cvt.u32.u64 %0, t; }"
        : "=r"(a) : "l"(p));
    return a;
}
#define CP_ASYNC16(dst, src) \
    asm volatile("cp.async.cg.shared.global [%0], [%1], 16;" \
                 :: "r"(dst), "l"(src) : "memory")
#define CP_COMMIT() asm volatile("cp.async.commit_group;" ::: "memory")
#define CP_WAIT(n)  asm volatile("cp.async.wait_group %0;" :: "n"(n) : "memory")

__device__ __forceinline__ float2 bf2f(uint32_t u) {
    __nv_bfloat162 h;
    *reinterpret_cast<uint32_t*>(&h) = u;
    return __bfloat1622float2(h);
}

// ldmatrix x4: four 8x8 b16 tiles, addresses supplied per-lane
__device__ __forceinline__ void ldmx4(uint32_t* r, uint32_t addr) {
    asm volatile(
        "ldmatrix.sync.aligned.m8n8.x4.shared.b16 {%0,%1,%2,%3}, [%4];"
        : "=r"(r[0]), "=r"(r[1]), "=r"(r[2]), "=r"(r[3]) : "r"(addr));
}

// warp-level bf16 MMA: D(16x8,f32) += A(16x16) * B(16x8)
__device__ __forceinline__ void mma_bf16(float* d, const uint32_t* a,
                                         uint32_t b0, uint32_t b1) {
    asm volatile(
        "mma.sync.aligned.m16n8k16.row.col.f32.bf16.bf16.f32 "
        "{%0,%1,%2,%3}, {%4,%5,%6,%7}, {%8,%9}, {%0,%1,%2,%3};"
        : "+f"(d[0]), "+f"(d[1]), "+f"(d[2]), "+f"(d[3])
        : "r"(a[0]), "r"(a[1]), "r"(a[2]), "r"(a[3]), "r"(b0), "r"(b1));
}

// ---------------- 1. MSE partials (deterministic two-stage) ------------------
__global__ void __launch_bounds__(256) mse_kernel(const float* __restrict__ o,
                                                  const float* __restrict__ t,
                                                  const float* __restrict__ of,
                                                  const float* __restrict__ tf) {
    const int which = blockIdx.y;
    const float* a = which ? of : o;
    const float* c = which ? tf : t;
    const int n = which ? FEAT_ELEMS : IMG_ELEMS;
    double s = 0.0;
    for (int i = blockIdx.x * 256 + threadIdx.x; i < n; i += 512 * 256) {
        float d = a[i] - c[i];
        s += (double)d * (double)d;
    }
    __shared__ double sh[256];
    sh[threadIdx.x] = s;
    __syncthreads();
    for (int st = 128; st > 0; st >>= 1) {
        if (threadIdx.x < st) sh[threadIdx.x] += sh[threadIdx.x + st];
        __syncthreads();
    }
    if (threadIdx.x == 0) g_msep[which][blockIdx.x] = sh[0];
}

// ---------------- 2. per-(b,c) means over N positions ------------------------
__global__ void __launch_bounds__(256) mean_kernel(const float* __restrict__ of,
                                                   const float* __restrict__ tf) {
    const float* src = blockIdx.y ? tf : of;
    const int bc = blockIdx.x;
    const float* p = src + (size_t)bc * Nn;
    float s = 0.f;
    for (int i = threadIdx.x; i < Nn; i += 256) s += p[i];
    __shared__ float sh[256];
    sh[threadIdx.x] = s;
    __syncthreads();
    for (int st = 128; st > 0; st >>= 1) {
        if (threadIdx.x < st) sh[threadIdx.x] += sh[threadIdx.x + st];
        __syncthreads();
    }
    if (threadIdx.x == 0) g_mean[blockIdx.y][bc] = sh[0] * (1.f / Nn);
}

// ---------------- 3. transpose [C][N] -> [N][C], center, cast bf16 -----------
__global__ void __launch_bounds__(256) transpose_kernel(const float* __restrict__ of,
                                                        const float* __restrict__ tf) {
    const int tz = blockIdx.z;
    const int tensor = tz >> 2;
    const int b = tz & 3;
    const float* src = (tensor ? tf : of) + (size_t)b * Cn * Nn;
    __nv_bfloat16* dst = (tensor ? g_Yh : g_Xh) + (size_t)b * Nn * Cn;
    const float* mean = g_mean[tensor] + b * Cn;
    __shared__ float tile[32][33];
    const int tx = threadIdx.x, ty = threadIdx.y;  // 32 x 8
    const int n0 = blockIdx.x * 32, c0 = blockIdx.y * 32;
#pragma unroll
    for (int j = 0; j < 4; j++) {
        int c = c0 + ty + j * 8;
        tile[ty + j * 8][tx] = src[(size_t)c * Nn + n0 + tx] - mean[c];
    }
    __syncthreads();
#pragma unroll
    for (int j = 0; j < 4; j++) {
        int n = n0 + ty + j * 8;
        dst[(size_t)n * Cn + c0 + tx] = __float2bfloat16(tile[tx][ty + j * 8]);
    }
}

// ---------------- 4. per-row L2 norms (from bf16 rows) ------------------------
__global__ void __launch_bounds__(256) norm_kernel() {
    const int tensor = blockIdx.y;
    const __nv_bfloat16* X = tensor ? g_Yh : g_Xh;
    float* out = tensor ? g_yn : g_xn;
    const int warp = threadIdx.x >> 5, lane = threadIdx.x & 31;
    const int r = blockIdx.x * 8 + warp;
    const uint4* p = (const uint4*)(X + (size_t)r * Cn);
    uint4 q = p[lane];  // 8 bf16
    const uint32_t* w = (const uint32_t*)&q;
    float s = 0.f;
#pragma unroll
    for (int i = 0; i < 4; i++) {
        float2 f = bf2f(w[i]);
        s += f.x * f.x + f.y * f.y;
    }
    for (int o = 16; o; o >>= 1) s += __shfl_xor_sync(0xffffffffu, s, o);
    if (lane == 0) out[r] = sqrtf(s);
}

// ---------------- 5. bf16 mma.sync GEMM -> bf16 cosine matrix ----------------
// BM=128, BN=128, BK=32, 256 threads (8 warps, 2x4 grid, warp tile 64x32).
// 3-stage cp.async pipeline (prefetch depth 2) hides L2 latency.
// Fragment loads via ldmatrix.x4. Smem rows = 64 B; XOR swizzle on 16B groups:
// grp ^= (row>>1)&3 -> ldmatrix phases and cp.async stores conflict-free.
__global__ void __launch_bounds__(256) gemm_mma_kernel() {
    __shared__ __align__(16) uint32_t smem[12288];  // 3 stages x (A 8KB | B 8KB)

    const int b = blockIdx.z;
    const int rowBase = blockIdx.y * 128, colBase = blockIdx.x * 128;
    const __nv_bfloat16* __restrict__ Xb = g_Xh + (size_t)b * (Nn * Cn);
    const __nv_bfloat16* __restrict__ Yb = g_Yh + (size_t)b * (Nn * Cn);
    const int tid = threadIdx.x;
    const int wid = tid >> 5, lane = tid & 31;
    const int wm = wid & 1, wn = wid >> 1;   // 2 along M, 4 along N
    const int g = lane >> 2, c = lane & 3;

    // cp.async staging: 128 rows x 64 B per operand per chunk; 2 xfers/thread/op
    const int row0 = tid >> 2, tq = tid & 3;
    const __nv_bfloat16* Agp = Xb + (size_t)(rowBase + row0) * Cn + tq * 8;
    const __nv_bfloat16* Bgp = Yb + (size_t)(colBase + row0) * Cn + tq * 8;
    const uint32_t sbase = smem_u32(smem);
    const uint32_t soff = (uint32_t)(row0 * 64 + (tq ^ ((row0 >> 1) & 3)) * 16);

#define ISSUE(ch, st) do {                                                    \
        const uint32_t dA = sbase + (uint32_t)(st) * 16384u + soff;           \
        const uint32_t dB = dA + 8192u;                                       \
        CP_ASYNC16(dA,        Agp + (ch) * 32);                               \
        CP_ASYNC16(dA + 4096, Agp + 64 * Cn + (ch) * 32);                     \
        CP_ASYNC16(dB,        Bgp + (ch) * 32);                               \
        CP_ASYNC16(dB + 4096, Bgp + 64 * Cn + (ch) * 32);                     \
        CP_COMMIT();                                                          \
    } while (0)

    float d[4][4][4];
#pragma unroll
    for (int mt = 0; mt < 4; mt++)
#pragma unroll
        for (int nt = 0; nt < 4; nt++)
#pragma unroll
            for (int k = 0; k < 4; k++) d[mt][nt][k] = 0.f;

    // ldmatrix per-lane address geometry
    const int arow = wm * 64 + (lane & 15);        // + mt*16
    const int ahi = lane >> 4;                     // k-halfgroup select
    const uint32_t asw = (uint32_t)((arow >> 1) & 3);
    const uint32_t aoff = (uint32_t)(arow * 64);
    const int brow = wn * 32 + lane;               // covers 4 n-tiles of 8 rows
    const uint32_t bsw = (uint32_t)((brow >> 1) & 3);
    const uint32_t boff = 8192u + (uint32_t)(brow * 64);

    ISSUE(0, 0);
    ISSUE(1, 1);
    int stage = 0;
    for (int ch = 0; ch < 8; ch++) {
        if (ch < 6) {
            int nst = stage + 2; if (nst >= 3) nst -= 3;
            ISSUE(ch + 2, nst);
            CP_WAIT(2);
        } else if (ch == 6) {
            CP_WAIT(1);
        } else {
            CP_WAIT(0);
        }
        __syncthreads();

        const uint32_t sb = sbase + (uint32_t)stage * 16384u;
        const uint32_t abase = sb + aoff;
        const uint32_t bbase = sb + boff;
#pragma unroll
        for (int kk = 0; kk < 2; kk++) {
            uint32_t af[4][4], b0[4], b1[4];
            const uint32_t akg = (uint32_t)(kk * 2 + ahi);
#pragma unroll
            for (int mt = 0; mt < 4; mt++)
                ldmx4(af[mt], abase + (uint32_t)(mt * 1024) + ((akg ^ asw) << 4));
            ldmx4(b0, bbase + (((uint32_t)(kk * 2) ^ bsw) << 4));
            ldmx4(b1, bbase + (((uint32_t)(kk * 2 + 1) ^ bsw) << 4));
#pragma unroll
            for (int mt = 0; mt < 4; mt++)
#pragma unroll
                for (int nt = 0; nt < 4; nt++)
                    mma_bf16(d[mt][nt], af[mt], b0[nt], b1[nt]);
        }
        __syncthreads();
        if (++stage == 3) stage = 0;
    }
#undef ISSUE

    // ---- epilogue: cosine normalization + bf16 store ----
    const float* xn = g_xn + (b << 12);
    const float* yn = g_yn + (b << 12);
    float xv[4][2], yv[4][2];
#pragma unroll
    for (int mt = 0; mt < 4; mt++) {
        const int r = rowBase + wm * 64 + mt * 16 + g;
        xv[mt][0] = xn[r];
        xv[mt][1] = xn[r + 8];
    }
#pragma unroll
    for (int nt = 0; nt < 4; nt++) {
        const int cc = colBase + wn * 32 + nt * 8 + 2 * c;
        yv[nt][0] = yn[cc];
        yv[nt][1] = yn[cc + 1];
    }
    __nv_bfloat16* Cb = g_cosh + ((size_t)b << 24);
#pragma unroll
    for (int mt = 0; mt < 4; mt++) {
        const int r = rowBase + wm * 64 + mt * 16 + g;
#pragma unroll
        for (int nt = 0; nt < 4; nt++) {
            const int cc = colBase + wn * 32 + nt * 8 + 2 * c;
            __nv_bfloat162 o0 = __floats2bfloat162_rn(
                d[mt][nt][0] / (xv[mt][0] * yv[nt][0] + EPS1),
                d[mt][nt][1] / (xv[mt][0] * yv[nt][1] + EPS1));
            __nv_bfloat162 o1 = __floats2bfloat162_rn(
                d[mt][nt][2] / (xv[mt][1] * yv[nt][0] + EPS1),
                d[mt][nt][3] / (xv[mt][1] * yv[nt][1] + EPS1));
            *(__nv_bfloat162*)(Cb + (size_t)r * Nn + cc) = o0;
            *(__nv_bfloat162*)(Cb + (size_t)(r + 8) * Nn + cc) = o1;
        }
    }
}

// ---------------- 6. row pass: warp-per-row, shfl-only reductions -------------
// d = 1-cos; s = 1/(dmin+eps2); w_y = exp((1-s) + cos_y*s)
__global__ void __launch_bounds__(256) rowpass_kernel() {
    const int warp = threadIdx.x >> 5, lane = threadIdx.x & 31;
    const int r = blockIdx.x * 8 + warp;  // b*Nn + x
    const uint4* row = (const uint4*)(g_cosh + (size_t)r * Nn);
    uint4 q[16];
#pragma unroll
    for (int j = 0; j < 16; j++) q[j] = row[lane + 32 * j];

    float m = -1e30f;
#pragma unroll
    for (int j = 0; j < 16; j++) {
        const uint32_t* w = (const uint32_t*)&q[j];
#pragma unroll
        for (int i = 0; i < 4; i++) {
            float2 f = bf2f(w[i]);
            m = fmaxf(m, fmaxf(f.x, f.y));
        }
    }
    for (int o = 16; o; o >>= 1) m = fmaxf(m, __shfl_xor_sync(0xffffffffu, m, o));

    const float s = 1.f / (1.f - m + EPS2);
    const float a = 1.f - s;
    float sum = 0.f;
#pragma unroll
    for (int j = 0; j < 16; j++) {
        const uint32_t* w = (const uint32_t*)&q[j];
#pragma unroll
        for (int i = 0; i < 4; i++) {
            float2 f = bf2f(w[i]);
            sum += __expf(fmaf(f.x, s, a)) + __expf(fmaf(f.y, s, a));
        }
    }
    for (int o = 16; o; o >>= 1) sum += __shfl_xor_sync(0xffffffffu, sum, o);

    if (lane == 0) {
        g_pS[r] = s;
        g_pA[r] = a - logf(sum);
    }
}

// ---------------- 7. column pass: partial max over x (log-domain) ------------
// log c[x][y] = cos*s_x + A_x -> max over 512-row x-chunk, 2 y per thread
__global__ void __launch_bounds__(256) colpass_kernel() {
    const int tid = threadIdx.x;
    const int ypair = blockIdx.x * 256 + tid;  // 0..2047 (y = 2*ypair)
    const int chunk = blockIdx.y;              // 0..7
    const int b = blockIdx.z;                  // 0..3
    __shared__ float ss[512], sa[512];
    const int r0 = (b << 12) + (chunk << 9);
    for (int i = tid; i < 512; i += 256) {
        ss[i] = g_pS[r0 + i];
        sa[i] = g_pA[r0 + i];
    }
    __syncthreads();
    const uint32_t* base =
        (const uint32_t*)(g_cosh + ((size_t)b << 24) + ((size_t)chunk << 21)) + ypair;
    float m0 = -1e30f, m1 = -1e30f;
#pragma unroll 8
    for (int x = 0; x < 512; x++) {
        float2 f = bf2f(base[(size_t)x << 11]);
        m0 = fmaxf(m0, fmaf(f.x, ss[x], sa[x]));
        m1 = fmaxf(m1, fmaf(f.y, ss[x], sa[x]));
    }
    const int y = ypair * 2;
    g_cmax[(chunk << 14) + (b << 12) + y] = m0;
    g_cmax[(chunk << 14) + (b << 12) + y + 1] = m1;
}

// ---------------- 8. final: CS, MSEs, loss -----------------------------------
__global__ void __launch_bounds__(256) final_kernel(float* __restrict__ out) {
    const int tid = threadIdx.x;
    double cs = 0.0;
    for (int i = tid; i < Bn * Nn; i += 256) {
        float m = -1e30f;
#pragma unroll
        for (int ch = 0; ch < 8; ch++) m = fmaxf(m, g_cmax[(ch << 14) + i]);
        cs += exp((double)m);
    }
    double m1 = 0.0, m2 = 0.0;
    for (int i = tid; i < 512; i += 256) {
        m1 += g_msep[0][i];
        m2 += g_msep[1][i];
    }
    __shared__ double sh[3][256];
    sh[0][tid] = cs; sh[1][tid] = m1; sh[2][tid] = m2;
    __syncthreads();
    for (int st = 128; st > 0; st >>= 1) {
        if (tid < st) {
            sh[0][tid] += sh[0][tid + st];
            sh[1][tid] += sh[1][tid + st];
            sh[2][tid] += sh[2][tid + st];
        }
        __syncthreads();
    }
    if (tid == 0) {
        double CS = sh[0][0] / (double)(Bn * Nn);
        double mse1 = sh[1][0] / (double)IMG_ELEMS;
        double perc = sh[2][0] / (double)FEAT_ELEMS;
        out[0] = (float)(mse1 - log(CS) + 0.02 * perc);
    }
}

// ---------------- launch ------------------------------------------------------
extern "C" void kernel_launch(void* const* d_in, const int* in_sizes, int n_in,
                              void* d_out, int out_size) {
    const float* outputs = (const float*)d_in[0];
    const float* targets = (const float*)d_in[1];
    const float* of = (const float*)d_in[2];
    const float* tf = (const float*)d_in[3];
    float* out = (float*)d_out;

    mse_kernel<<<dim3(512, 2), 256>>>(outputs, targets, of, tf);
    mean_kernel<<<dim3(Bn * Cn, 2), 256>>>(of, tf);
    transpose_kernel<<<dim3(Nn / 32, Cn / 32, 2 * Bn), dim3(32, 8)>>>(of, tf);
    norm_kernel<<<dim3(Bn * Nn / 8, 2), 256>>>();
    gemm_mma_kernel<<<dim3(Nn / 128, Nn / 128, Bn), 256>>>();
    rowpass_kernel<<<Bn * Nn / 8, 256>>>();
    colpass_kernel<<<dim3(Nn / 512, 8, Bn), 256>>>();
    final_kernel<<<1, 256>>>(out);
}